// round 14
// baseline (speedup 1.0000x reference)
#include <cuda_runtime.h>

// SimpleTTS decoder-only. Recurrence folded to h-only:
//   g_t = Wcomb @ h_{t-1} + bcomb,  Wcomb = dec_Whh + dec_Wih @ lin_W
// Persistent 128-CTA kernel, weights register-resident (128 regs/thread).
// Handshake (R11-proven): h words ARE the sync variables (sentinel 2.0f).
// R14: h published to 8 REPLICA regions (8 release-stores per producer lane);
// consumer CTA ct polls only replica ct>>4 -> 16 pollers/chunk instead of
// 128, spread over 8x more L2 lines. Attacks the LTS queue-tail jitter that
// the backoff curve (16/32/64ns -> 1665/1585/1553us) exposed.

#define HID   1024
#define GATES 4096
#define MEL   80
#define NCTA  128
#define JPC   8
#define NTHR  256          // 8 warps
#define GRID  148
#define MAXT  1024
#define TT    8
#define NREP  8
#define SENT  0x40000000u  // 2.0f  (unreachable: |h| = |sig*tanh| < 1)

__device__ float d_Wcomb[GATES * HID];          // 16.7 MB
__device__ float d_bcomb[GATES];
__device__ float d_b0[GATES];
__device__ float d_hrep[NREP][MAXT * HID];      // 32 MB, sentinel-poisoned

__device__ __forceinline__ float fast_sig(float x) {
    return __fdividef(1.0f, 1.0f + __expf(-x));
}
__device__ __forceinline__ float fast_tanh(float x) {
    x = fminf(fmaxf(x, -15.0f), 15.0f);
    float e = __expf(-2.0f * x);
    return __fdividef(1.0f - e, 1.0f + e);
}
__device__ __forceinline__ void fma2(unsigned long long& acc,
                                     unsigned long long a, unsigned long long b) {
    asm("fma.rn.f32x2 %0, %1, %2, %0;" : "+l"(acc) : "l"(a), "l"(b));
}
__device__ __forceinline__ float2 unpack2(unsigned long long v) {
    float2 r;
    asm("mov.b64 {%0,%1}, %2;" : "=f"(r.x), "=f"(r.y) : "l"(v));
    return r;
}
// Acquire-poll one 16B chunk; every word validated against the sentinel.
__device__ __forceinline__ uint4 poll_v4_acq(const uint4* p) {
    uint4 v;
    for (;;) {
        asm volatile("ld.acquire.gpu.global.v4.u32 {%0,%1,%2,%3}, [%4];"
                     : "=r"(v.x), "=r"(v.y), "=r"(v.z), "=r"(v.w)
                     : "l"(p) : "memory");
        if (v.x != SENT && v.y != SENT && v.z != SENT && v.w != SENT) return v;
        __nanosleep(64);
    }
}
__device__ __forceinline__ void st_release_f32(float* p, float v) {
    asm volatile("st.release.gpu.global.f32 [%0], %1;" :: "l"(p), "f"(v) : "memory");
}
// Publish one h word to all 8 replicas (fire-and-forget; visibility overlaps).
__device__ __forceinline__ void publish_h(size_t off, float v) {
    #pragma unroll
    for (int r = 0; r < NREP; ++r)
        st_release_f32(&d_hrep[r][0] + (size_t)r * 0 + off + (size_t)r * (MAXT * HID) * 0, v),
        (void)0;
}

// ---------------------------------------------------------------------------
// Prep: Wcomb = Whh + Wih @ lin_W, biases, FULL sentinel poison of all
// replicas (256 blocks x 256 thr x 32 uint4 = 2,097,152 uint4 = exact size).
// ---------------------------------------------------------------------------
__global__ void prep(const float* __restrict__ Wih,
                     const float* __restrict__ Whh,
                     const float* __restrict__ linW,
                     const float* __restrict__ bih,
                     const float* __restrict__ bhh,
                     const float* __restrict__ linb) {
    __shared__ float wih_s[16 * MEL];
    const int r0 = blockIdx.x * 16;
    for (int i = threadIdx.x; i < 16 * MEL; i += 256)
        wih_s[i] = Wih[r0 * MEL + i];
    __syncthreads();

    for (int c = threadIdx.x; c < HID; c += 256) {
        float acc[16];
        #pragma unroll
        for (int r = 0; r < 16; ++r) acc[r] = 0.0f;
        for (int k = 0; k < MEL; ++k) {
            float lw = __ldg(linW + (size_t)k * HID + c);
            #pragma unroll
            for (int r = 0; r < 16; ++r) acc[r] = fmaf(wih_s[r * MEL + k], lw, acc[r]);
        }
        #pragma unroll
        for (int r = 0; r < 16; ++r)
            d_Wcomb[(size_t)(r0 + r) * HID + c] =
                Whh[(size_t)(r0 + r) * HID + c] + acc[r];
    }

    if (threadIdx.x < 16) {
        int g = r0 + threadIdx.x;
        float s = bih[g] + bhh[g];
        d_b0[g] = s;
        float a = 0.0f;
        #pragma unroll 8
        for (int k = 0; k < MEL; ++k) a = fmaf(wih_s[threadIdx.x * MEL + k], linb[k], a);
        d_bcomb[g] = s + a;
    }

    {   // full poison of all 8 replicas, exact bounds, coalesced
        const uint4 poison = make_uint4(SENT, SENT, SENT, SENT);
        uint4* hh = (uint4*)d_hrep;
        int gid = blockIdx.x * 256 + threadIdx.x;   // 0..65535
        #pragma unroll
        for (int k = 0; k < 32; ++k) hh[(size_t)k * 65536 + gid] = poison;
    }
}

// ---------------------------------------------------------------------------
// Persistent recurrence + fused finalize. 148 CTAs launched; 128 work.
// 8 dot warps; warp w owns h cols [128w, 128w+128). Lane l owns gate-row
//   grow = (l>>3)*HID + ct*JPC + (l&7).
// Warp 0 is also the tail warp (reduce + activations + 8-replica publish).
// Consumer CTA ct polls ONLY replica ct>>4 (16 pollers per chunk).
// ---------------------------------------------------------------------------
__global__ void __launch_bounds__(NTHR, 1) tts_main(float* __restrict__ out,
                                                    const float* __restrict__ linW,
                                                    const float* __restrict__ linb,
                                                    int T, int B) {
    if (blockIdx.x >= NCTA) return;

    __shared__ float h_all[TT * HID];       // main loop uses first HID floats
    __shared__ float red_s[2][256];
    __shared__ float fr[TT][MEL];

    const int tid = threadIdx.x;
    const int w   = tid >> 5;
    const int l   = tid & 31;
    const int ct  = blockIdx.x;
    const int jj  = l & 7;
    const int grow = (l >> 3) * HID + ct * JPC + jj;
    float* const myrep = d_hrep[ct >> 4];   // replica this CTA polls

    // 128-float register weight slice packed as 64 f32x2.
    unsigned long long W2[64];
    {
        const longlong2* wg =
            (const longlong2*)(d_Wcomb + (size_t)grow * HID + (w << 7));
        #pragma unroll
        for (int k = 0; k < 32; ++k) {
            longlong2 v = wg[k];
            W2[2 * k]     = (unsigned long long)v.x;
            W2[2 * k + 1] = (unsigned long long)v.y;
        }
    }
    const float bc = d_bcomb[grow];
    float c = 0.0f;

    // ---- step 0 (h = x = 0): warp 0 computes from b0, publishes 8x ----
    if (w == 0) {
        float gv = d_b0[grow];
        float vi = __shfl_sync(0xffffffffu, gv, jj);
        float vg = __shfl_sync(0xffffffffu, gv, jj + 16);
        float vo = __shfl_sync(0xffffffffu, gv, jj + 24);
        if (l < 8) {
            c = fast_sig(vi) * fast_tanh(vg);
            float hh = fast_sig(vo) * fast_tanh(c);
            const size_t off = (size_t)ct * JPC + l;
            #pragma unroll
            for (int r = 0; r < NREP; ++r)
                st_release_f32(d_hrep[r] + off, hh);
        }
    }

    // ---- steps 1..T-1 ----
    for (int t = 1; t < T; ++t) {
        // each lane acquire-polls its own 16B chunk of h[t-1] (own replica)
        {
            const uint4* src =
                (const uint4*)(myrep + (size_t)(t - 1) * HID + (w << 7)) + l;
            uint4 hv = poll_v4_acq(src);
            ((uint4*)(h_all + (w << 7)))[l] = hv;
        }
        __syncwarp();

        // packed 128-wide dot, h broadcast from SMEM
        unsigned long long a0 = 0ull, a1 = 0ull;
        const longlong2* h2 = (const longlong2*)(h_all + (w << 7));
        #pragma unroll
        for (int k = 0; k < 32; ++k) {
            longlong2 hx = h2[k];
            fma2(a0, W2[2 * k],     (unsigned long long)hx.x);
            fma2(a1, W2[2 * k + 1], (unsigned long long)hx.y);
        }
        float2 p0 = unpack2(a0), p1 = unpack2(a1);
        red_s[t & 1][l * 8 + w] = (p0.x + p0.y) + (p1.x + p1.y);
        __syncthreads();

        if (w == 0) {
            const float4* rr = (const float4*)(&red_s[t & 1][l * 8]);
            float4 x0 = rr[0], x1 = rr[1];
            float gv = ((x0.x + x0.y) + (x0.z + x0.w)) +
                       ((x1.x + x1.y) + (x1.z + x1.w)) + bc;
            float vi = __shfl_sync(0xffffffffu, gv, jj);
            float vf = __shfl_sync(0xffffffffu, gv, jj + 8);
            float vg = __shfl_sync(0xffffffffu, gv, jj + 16);
            float vo = __shfl_sync(0xffffffffu, gv, jj + 24);
            if (l < 8) {
                c = fast_sig(vf) * c + fast_sig(vi) * fast_tanh(vg);
                float hh = fast_sig(vo) * fast_tanh(c);
                const size_t off = (size_t)t * HID + ct * JPC + l;
                #pragma unroll
                for (int r = 0; r < NREP; ++r)
                    st_release_f32(d_hrep[r] + off, hh);
            }
        }
        // red_s WAR safe: this parity is rewritten only at step t+2, after
        // the t+1 barrier, which warp 0 reaches only after this tail.
        // h_all slice WAR safe: rewritten only by the same warp's next poll.
    }

    // ===== fused finalize: CTA ct -> timesteps [ct*TT, ct*TT+TT) =====
    const int t0 = ct * TT;
    if (t0 < T) {
        for (int i = tid; i < TT * HID / 4; i += NTHR) {
            int j = i >> 8;                 // / (HID/4)
            int k = i & 255;                // uint4 index within row
            if (t0 + j < T) {
                uint4 hv = poll_v4_acq(
                    (const uint4*)(myrep + (size_t)(t0 + j) * HID) + k);
                ((uint4*)(h_all + j * HID))[k] = hv;
            }
        }
        __syncthreads();

        for (int m = w; m < MEL; m += 8) {
            const float* wrow = linW + (size_t)m * HID;
            float s[TT];
            #pragma unroll
            for (int j = 0; j < TT; ++j) s[j] = 0.0f;
            for (int k = l; k < HID; k += 32) {
                float wv = wrow[k];
                #pragma unroll
                for (int j = 0; j < TT; ++j) s[j] = fmaf(wv, h_all[j * HID + k], s[j]);
            }
            #pragma unroll
            for (int j = 0; j < TT; ++j) {
                #pragma unroll
                for (int off = 16; off; off >>= 1)
                    s[j] += __shfl_down_sync(0xffffffffu, s[j], off);
            }
            if (l == 0) {
                float bb = linb[m];
                #pragma unroll
                for (int j = 0; j < TT; ++j) fr[j][m] = s[j] + bb;
            }
        }
        __syncthreads();

        const int tot = B * TT * MEL;
        for (int i = tid; i < tot; i += NTHR) {
            int b = i / (TT * MEL);
            int r = i - b * (TT * MEL);
            int j = r / MEL;
            int m = r - j * MEL;
            int t = t0 + j;
            if (t < T) out[((size_t)b * T + t) * MEL + m] = fr[j][m];
        }
    }
}

// ---------------------------------------------------------------------------
extern "C" void kernel_launch(void* const* d_in, const int* in_sizes, int n_in,
                              void* d_out, int out_size) {
    if (n_in < 6) return;
    const float* dec_Wih = (const float*)d_in[n_in - 6];
    const float* dec_Whh = (const float*)d_in[n_in - 5];
    const float* dec_bih = (const float*)d_in[n_in - 4];
    const float* dec_bhh = (const float*)d_in[n_in - 3];
    const float* lin_W   = (const float*)d_in[n_in - 2];
    const float* lin_b   = (const float*)d_in[n_in - 1];

    const int B = in_sizes[1];
    int T = out_size / (B * MEL);
    if (T > MAXT) T = MAXT;
    if (T <= 0) return;

    prep    <<<GATES / 16, 256>>>(dec_Wih, dec_Whh, lin_W, dec_bih, dec_bhh, lin_b);
    tts_main<<<GRID, NTHR>>>((float*)d_out, lin_W, lin_b, T, B);
}

// round 15
// speedup vs baseline: 2.4785x; 2.4785x over previous
#include <cuda_runtime.h>

// SimpleTTS decoder-only. Recurrence folded to h-only:
//   g_t = Wcomb @ h_{t-1} + bcomb,  Wcomb = dec_Whh + dec_Wih @ lin_W
// Persistent 128-CTA kernel, weights register-resident (128 regs/thread).
// Handshake (R11/R13-proven): h words ARE the sync variables (sentinel 2.0f,
// unreachable since |h| < 1): st.release per word / ld.acquire.v4 spin.
// R15: 4 h replicas published by ONE 32-lane release-store (all lanes
// redundantly compute c/h for element l&7 -- gate values are already
// broadcast to all lanes -- lane l stores to replica l>>3). Consumer CTA ct
// polls replica ct>>5 -> 32 pollers/chunk instead of 128, zero extra
// producer instructions (R14's fan-out loop serialized 8 releases: 2.4x
// regression; this gets the same contention relief for free).

#define HID   1024
#define GATES 4096
#define MEL   80
#define NCTA  128
#define JPC   8
#define NTHR  256          // 8 warps
#define GRID  148
#define MAXT  1024
#define TT    8
#define NREP  4
#define SENT  0x40000000u  // 2.0f

__device__ float d_Wcomb[GATES * HID];          // 16.7 MB
__device__ float d_bcomb[GATES];
__device__ float d_b0[GATES];
__device__ float d_hrep[NREP][MAXT * HID];      // 16 MB, sentinel-poisoned

__device__ __forceinline__ float fast_sig(float x) {
    return __fdividef(1.0f, 1.0f + __expf(-x));
}
__device__ __forceinline__ float fast_tanh(float x) {
    x = fminf(fmaxf(x, -15.0f), 15.0f);
    float e = __expf(-2.0f * x);
    return __fdividef(1.0f - e, 1.0f + e);
}
__device__ __forceinline__ void fma2(unsigned long long& acc,
                                     unsigned long long a, unsigned long long b) {
    asm("fma.rn.f32x2 %0, %1, %2, %0;" : "+l"(acc) : "l"(a), "l"(b));
}
__device__ __forceinline__ float2 unpack2(unsigned long long v) {
    float2 r;
    asm("mov.b64 {%0,%1}, %2;" : "=f"(r.x), "=f"(r.y) : "l"(v));
    return r;
}
// Acquire-poll one 16B chunk; every word validated against the sentinel.
__device__ __forceinline__ uint4 poll_v4_acq(const uint4* p) {
    uint4 v;
    for (;;) {
        asm volatile("ld.acquire.gpu.global.v4.u32 {%0,%1,%2,%3}, [%4];"
                     : "=r"(v.x), "=r"(v.y), "=r"(v.z), "=r"(v.w)
                     : "l"(p) : "memory");
        if (v.x != SENT && v.y != SENT && v.z != SENT && v.w != SENT) return v;
        __nanosleep(64);
    }
}
__device__ __forceinline__ void st_release_f32(float* p, float v) {
    asm volatile("st.release.gpu.global.f32 [%0], %1;" :: "l"(p), "f"(v) : "memory");
}

// ---------------------------------------------------------------------------
// Prep: Wcomb = Whh + Wih @ lin_W, biases, FULL sentinel poison of all
// 4 replicas (65,536 threads x 16 uint4 = 1,048,576 uint4 = exact size).
// ---------------------------------------------------------------------------
__global__ void prep(const float* __restrict__ Wih,
                     const float* __restrict__ Whh,
                     const float* __restrict__ linW,
                     const float* __restrict__ bih,
                     const float* __restrict__ bhh,
                     const float* __restrict__ linb) {
    __shared__ float wih_s[16 * MEL];
    const int r0 = blockIdx.x * 16;
    for (int i = threadIdx.x; i < 16 * MEL; i += 256)
        wih_s[i] = Wih[r0 * MEL + i];
    __syncthreads();

    for (int c = threadIdx.x; c < HID; c += 256) {
        float acc[16];
        #pragma unroll
        for (int r = 0; r < 16; ++r) acc[r] = 0.0f;
        for (int k = 0; k < MEL; ++k) {
            float lw = __ldg(linW + (size_t)k * HID + c);
            #pragma unroll
            for (int r = 0; r < 16; ++r) acc[r] = fmaf(wih_s[r * MEL + k], lw, acc[r]);
        }
        #pragma unroll
        for (int r = 0; r < 16; ++r)
            d_Wcomb[(size_t)(r0 + r) * HID + c] =
                Whh[(size_t)(r0 + r) * HID + c] + acc[r];
    }

    if (threadIdx.x < 16) {
        int g = r0 + threadIdx.x;
        float s = bih[g] + bhh[g];
        d_b0[g] = s;
        float a = 0.0f;
        #pragma unroll 8
        for (int k = 0; k < MEL; ++k) a = fmaf(wih_s[threadIdx.x * MEL + k], linb[k], a);
        d_bcomb[g] = s + a;
    }

    {   // full poison of all 4 replicas, exact bounds, coalesced
        const uint4 poison = make_uint4(SENT, SENT, SENT, SENT);
        uint4* hh = (uint4*)d_hrep;
        int gid = blockIdx.x * 256 + threadIdx.x;   // 0..65535
        #pragma unroll
        for (int k = 0; k < 16; ++k) hh[(size_t)k * 65536 + gid] = poison;
    }
}

// ---------------------------------------------------------------------------
// Persistent recurrence + fused finalize. 148 CTAs launched; 128 work.
// 8 dot warps; warp w owns h cols [128w, 128w+128). Lane l owns gate-row
//   grow = (l>>3)*HID + ct*JPC + (l&7).
// Warp 0 tail: ALL 32 lanes compute c/h for element l&7 (redundant per
// 8-lane group); lane l release-stores to replica l>>3 (one instruction).
// Consumer CTA ct polls only replica ct>>5.
// ---------------------------------------------------------------------------
__global__ void __launch_bounds__(NTHR, 1) tts_main(float* __restrict__ out,
                                                    const float* __restrict__ linW,
                                                    const float* __restrict__ linb,
                                                    int T, int B) {
    if (blockIdx.x >= NCTA) return;

    __shared__ float h_all[TT * HID];       // main loop uses first HID floats
    __shared__ float red_s[2][256];
    __shared__ float fr[TT][MEL];

    const int tid = threadIdx.x;
    const int w   = tid >> 5;
    const int l   = tid & 31;
    const int ct  = blockIdx.x;
    const int jj  = l & 7;
    const int grow = (l >> 3) * HID + ct * JPC + jj;
    float* const myrep  = d_hrep[ct >> 5];          // replica this CTA polls
    float* const pubrep = d_hrep[l >> 3];           // replica this lane writes

    // 128-float register weight slice packed as 64 f32x2.
    unsigned long long W2[64];
    {
        const longlong2* wg =
            (const longlong2*)(d_Wcomb + (size_t)grow * HID + (w << 7));
        #pragma unroll
        for (int k = 0; k < 32; ++k) {
            longlong2 v = wg[k];
            W2[2 * k]     = (unsigned long long)v.x;
            W2[2 * k + 1] = (unsigned long long)v.y;
        }
    }
    const float bc = d_bcomb[grow];
    float c = 0.0f;   // warp 0: every lane carries c for element jj (replicated)

    // ---- step 0 (h = x = 0): warp 0, all lanes compute, 4-replica store ----
    if (w == 0) {
        float gv = d_b0[grow];
        float vi = __shfl_sync(0xffffffffu, gv, jj);
        float vg = __shfl_sync(0xffffffffu, gv, jj + 16);
        float vo = __shfl_sync(0xffffffffu, gv, jj + 24);
        c = fast_sig(vi) * fast_tanh(vg);
        float hh = fast_sig(vo) * fast_tanh(c);
        st_release_f32(pubrep + ct * JPC + jj, hh);
    }

    // ---- steps 1..T-1 ----
    for (int t = 1; t < T; ++t) {
        // each lane acquire-polls its own 16B chunk of h[t-1] (own replica)
        {
            const uint4* src =
                (const uint4*)(myrep + (size_t)(t - 1) * HID + (w << 7)) + l;
            uint4 hv = poll_v4_acq(src);
            ((uint4*)(h_all + (w << 7)))[l] = hv;
        }
        __syncwarp();

        // packed 128-wide dot, h broadcast from SMEM
        unsigned long long a0 = 0ull, a1 = 0ull;
        const longlong2* h2 = (const longlong2*)(h_all + (w << 7));
        #pragma unroll
        for (int k = 0; k < 32; ++k) {
            longlong2 hx = h2[k];
            fma2(a0, W2[2 * k],     (unsigned long long)hx.x);
            fma2(a1, W2[2 * k + 1], (unsigned long long)hx.y);
        }
        float2 p0 = unpack2(a0), p1 = unpack2(a1);
        red_s[t & 1][l * 8 + w] = (p0.x + p0.y) + (p1.x + p1.y);
        __syncthreads();

        if (w == 0) {
            const float4* rr = (const float4*)(&red_s[t & 1][l * 8]);
            float4 x0 = rr[0], x1 = rr[1];
            float gv = ((x0.x + x0.y) + (x0.z + x0.w)) +
                       ((x1.x + x1.y) + (x1.z + x1.w)) + bc;
            float vi = __shfl_sync(0xffffffffu, gv, jj);
            float vf = __shfl_sync(0xffffffffu, gv, jj + 8);
            float vg = __shfl_sync(0xffffffffu, gv, jj + 16);
            float vo = __shfl_sync(0xffffffffu, gv, jj + 24);
            // all 32 lanes: identical update for element jj (replicated state)
            c = fast_sig(vf) * c + fast_sig(vi) * fast_tanh(vg);
            float hh = fast_sig(vo) * fast_tanh(c);
            st_release_f32(pubrep + (size_t)t * HID + ct * JPC + jj, hh);
        }
        // red_s WAR safe: this parity is rewritten only at step t+2, after
        // the t+1 barrier, which warp 0 reaches only after this tail.
        // h_all slice WAR safe: rewritten only by the same warp's next poll.
    }

    // ===== fused finalize: CTA ct -> timesteps [ct*TT, ct*TT+TT) =====
    const int t0 = ct * TT;
    if (t0 < T) {
        for (int i = tid; i < TT * HID / 4; i += NTHR) {
            int j = i >> 8;                 // / (HID/4)
            int k = i & 255;                // uint4 index within row
            if (t0 + j < T) {
                uint4 hv = poll_v4_acq(
                    (const uint4*)(myrep + (size_t)(t0 + j) * HID) + k);
                ((uint4*)(h_all + j * HID))[k] = hv;
            }
        }
        __syncthreads();

        for (int m = w; m < MEL; m += 8) {
            const float* wrow = linW + (size_t)m * HID;
            float s[TT];
            #pragma unroll
            for (int j = 0; j < TT; ++j) s[j] = 0.0f;
            for (int k = l; k < HID; k += 32) {
                float wv = wrow[k];
                #pragma unroll
                for (int j = 0; j < TT; ++j) s[j] = fmaf(wv, h_all[j * HID + k], s[j]);
            }
            #pragma unroll
            for (int j = 0; j < TT; ++j) {
                #pragma unroll
                for (int off = 16; off; off >>= 1)
                    s[j] += __shfl_down_sync(0xffffffffu, s[j], off);
            }
            if (l == 0) {
                float bb = linb[m];
                #pragma unroll
                for (int j = 0; j < TT; ++j) fr[j][m] = s[j] + bb;
            }
        }
        __syncthreads();

        const int tot = B * TT * MEL;
        for (int i = tid; i < tot; i += NTHR) {
            int b = i / (TT * MEL);
            int r = i - b * (TT * MEL);
            int j = r / MEL;
            int m = r - j * MEL;
            int t = t0 + j;
            if (t < T) out[((size_t)b * T + t) * MEL + m] = fr[j][m];
        }
    }
}

// ---------------------------------------------------------------------------
extern "C" void kernel_launch(void* const* d_in, const int* in_sizes, int n_in,
                              void* d_out, int out_size) {
    if (n_in < 6) return;
    const float* dec_Wih = (const float*)d_in[n_in - 6];
    const float* dec_Whh = (const float*)d_in[n_in - 5];
    const float* dec_bih = (const float*)d_in[n_in - 4];
    const float* dec_bhh = (const float*)d_in[n_in - 3];
    const float* lin_W   = (const float*)d_in[n_in - 2];
    const float* lin_b   = (const float*)d_in[n_in - 1];

    const int B = in_sizes[1];
    int T = out_size / (B * MEL);
    if (T > MAXT) T = MAXT;
    if (T <= 0) return;

    prep    <<<GATES / 16, 256>>>(dec_Wih, dec_Whh, lin_W, dec_bih, dec_bhh, lin_b);
    tts_main<<<GRID, NTHR>>>((float*)d_out, lin_W, lin_b, T, B);
}